// round 4
// baseline (speedup 1.0000x reference)
#include <cuda_runtime.h>

// Tensors [B=64, S=100, K=4, H=32, W=32] fp32; only channel k=3 is read:
// contiguous 1024-float run at s*4096 + 3072 for each of 6400 (b,s) slices.
// result = mean(|convdata[:,:,3] - output[:,:,3]|) over 6400*1024 elements.

static constexpr int NUM_SLICES   = 64 * 100;    // 6400
static constexpr int SLICE_STRIDE = 4 * 32 * 32; // 4096 floats per (b,s)
static constexpr int CH3_OFFSET   = 3 * 32 * 32; // 3072
static constexpr int SLICE_ELEMS  = 32 * 32;     // 1024 floats

static constexpr int THREADS = 256;              // one float4 per thread per slice
static constexpr int BLOCKS  = 256;              // single wave: <= 148 SMs * 2 blocks
static constexpr int SLICES_PER_BLOCK = NUM_SLICES / BLOCKS;  // 25
static constexpr int CHUNK   = 5;                // slices per pipeline stage
static constexpr int NCHUNKS = SLICES_PER_BLOCK / CHUNK;      // 5

// Cross-block fan-in scratch (device globals: allocation-free).
// Invariant: zero at every launch; last finishing block re-zeros after publishing.
__device__ float        g_accum = 0.0f;
__device__ unsigned int g_count = 0u;

__global__ __launch_bounds__(THREADS, 2) void abs_diff_mean_kernel(
    const float* __restrict__ a,   // "output" tensor
    const float* __restrict__ b,   // "convdata" tensor
    float* __restrict__ res)
{
    const int tid = threadIdx.x;

    // This block's 25 contiguous slices; thread t owns one float4 per slice.
    const size_t base = (size_t)blockIdx.x * SLICES_PER_BLOCK * SLICE_STRIDE
                      + CH3_OFFSET + (size_t)tid * 4;
    const float* pa = a + base;
    const float* pb = b + base;

    float4 ca[CHUNK], cb[CHUNK];   // current chunk (being consumed)
    float4 na[CHUNK], nb[CHUNK];   // next chunk (in flight)

    // Prologue: load chunk 0 (10 independent LDG.128).
    #pragma unroll
    for (int i = 0; i < CHUNK; i++) {
        ca[i] = *reinterpret_cast<const float4*>(pa + i * SLICE_STRIDE);
        cb[i] = *reinterpret_cast<const float4*>(pb + i * SLICE_STRIDE);
    }

    float acc = 0.0f;

    // Steady state: prefetch chunk c, consume chunk c-1.
    #pragma unroll
    for (int c = 1; c < NCHUNKS; c++) {
        #pragma unroll
        for (int i = 0; i < CHUNK; i++) {
            const int s = c * CHUNK + i;
            na[i] = *reinterpret_cast<const float4*>(pa + s * SLICE_STRIDE);
            nb[i] = *reinterpret_cast<const float4*>(pb + s * SLICE_STRIDE);
        }
        #pragma unroll
        for (int i = 0; i < CHUNK; i++) {
            acc += fabsf(cb[i].x - ca[i].x) + fabsf(cb[i].y - ca[i].y)
                 + fabsf(cb[i].z - ca[i].z) + fabsf(cb[i].w - ca[i].w);
            ca[i] = na[i];
            cb[i] = nb[i];
        }
    }

    // Epilogue: consume final chunk.
    #pragma unroll
    for (int i = 0; i < CHUNK; i++) {
        acc += fabsf(cb[i].x - ca[i].x) + fabsf(cb[i].y - ca[i].y)
             + fabsf(cb[i].z - ca[i].z) + fabsf(cb[i].w - ca[i].w);
    }

    // Warp reduce
    #pragma unroll
    for (int off = 16; off > 0; off >>= 1)
        acc += __shfl_xor_sync(0xFFFFFFFFu, acc, off);

    __shared__ float warp_sums[THREADS / 32];
    if ((tid & 31) == 0) warp_sums[tid >> 5] = acc;
    __syncthreads();

    if (tid == 0) {
        float v = 0.0f;
        #pragma unroll
        for (int w = 0; w < THREADS / 32; w++) v += warp_sums[w];

        atomicAdd(&g_accum, v);
        __threadfence();
        unsigned int done = atomicAdd(&g_count, 1u);
        if (done == (unsigned)(gridDim.x - 1)) {
            float total = atomicExch(&g_accum, 0.0f);   // read + reset scratch
            const float inv_total = 1.0f / ((float)NUM_SLICES * (float)SLICE_ELEMS);
            res[0] = total * inv_total;
            g_count = 0u;                               // reset for next replay
        }
    }
}

extern "C" void kernel_launch(void* const* d_in, const int* in_sizes, int n_in,
                              void* d_out, int out_size) {
    const float* out_t  = (const float*)d_in[0];  // "output"
    const float* conv_t = (const float*)d_in[1];  // "convdata"
    float* res = (float*)d_out;

    abs_diff_mean_kernel<<<BLOCKS, THREADS>>>(out_t, conv_t, res);
}

// round 7
// speedup vs baseline: 1.2564x; 1.2564x over previous
#include <cuda_runtime.h>

// Tensors [B=64, S=100, K=4, H=32, W=32] fp32; only channel k=3 is read:
// contiguous 1024-float run at s*4096 + 3072 for each of 6400 (b,s) slices.
// result = mean(|convdata[:,:,3] - output[:,:,3]|) over 6400*1024 elements.

static constexpr int NUM_SLICES   = 64 * 100;    // 6400
static constexpr int SLICE_STRIDE = 4 * 32 * 32; // 4096 floats per (b,s)
static constexpr int CH3_OFFSET   = 3 * 32 * 32; // 3072
static constexpr int SLICE_ELEMS  = 32 * 32;     // 1024 floats

static constexpr int THREADS = 256;              // one float4 per thread per slice
static constexpr int BLOCKS  = 640;              // ~single wave at 4 CTAs/SM (592 slots)
static constexpr int SLICES_PER_BLOCK = NUM_SLICES / BLOCKS;  // 10
static constexpr int CHUNK   = 2;                // slices per pipeline stage (4 LDG.128)
static constexpr int NCHUNKS = SLICES_PER_BLOCK / CHUNK;      // 5

// Cross-block fan-in scratch (device globals: allocation-free).
// Invariant: zero at every launch; last finishing block re-zeros after publishing.
__device__ float        g_accum = 0.0f;
__device__ unsigned int g_count = 0u;

__global__ __launch_bounds__(THREADS, 4) void abs_diff_mean_kernel(
    const float* __restrict__ a,   // "output" tensor
    const float* __restrict__ b,   // "convdata" tensor
    float* __restrict__ res)
{
    const int tid = threadIdx.x;

    // This block's 10 contiguous slices; thread t owns one float4 per slice.
    const size_t base = (size_t)blockIdx.x * SLICES_PER_BLOCK * SLICE_STRIDE
                      + CH3_OFFSET + (size_t)tid * 4;
    const float* pa = a + base;
    const float* pb = b + base;

    float4 ca[CHUNK], cb[CHUNK];   // current chunk (being consumed)
    float4 na[CHUNK], nb[CHUNK];   // next chunk (in flight)

    // Prologue: chunk 0 in flight (4 independent LDG.128).
    #pragma unroll
    for (int i = 0; i < CHUNK; i++) {
        ca[i] = *reinterpret_cast<const float4*>(pa + i * SLICE_STRIDE);
        cb[i] = *reinterpret_cast<const float4*>(pb + i * SLICE_STRIDE);
    }

    float acc0 = 0.0f, acc1 = 0.0f;

    // Steady state: prefetch chunk c while consuming chunk c-1 (8 loads in flight).
    #pragma unroll
    for (int c = 1; c < NCHUNKS; c++) {
        #pragma unroll
        for (int i = 0; i < CHUNK; i++) {
            const int s = c * CHUNK + i;
            na[i] = *reinterpret_cast<const float4*>(pa + s * SLICE_STRIDE);
            nb[i] = *reinterpret_cast<const float4*>(pb + s * SLICE_STRIDE);
        }
        #pragma unroll
        for (int i = 0; i < CHUNK; i++) {
            acc0 += fabsf(cb[i].x - ca[i].x) + fabsf(cb[i].y - ca[i].y);
            acc1 += fabsf(cb[i].z - ca[i].z) + fabsf(cb[i].w - ca[i].w);
            ca[i] = na[i];
            cb[i] = nb[i];
        }
    }

    // Epilogue: consume final chunk.
    #pragma unroll
    for (int i = 0; i < CHUNK; i++) {
        acc0 += fabsf(cb[i].x - ca[i].x) + fabsf(cb[i].y - ca[i].y);
        acc1 += fabsf(cb[i].z - ca[i].z) + fabsf(cb[i].w - ca[i].w);
    }

    float acc = acc0 + acc1;

    // Warp reduce
    #pragma unroll
    for (int off = 16; off > 0; off >>= 1)
        acc += __shfl_xor_sync(0xFFFFFFFFu, acc, off);

    __shared__ float warp_sums[THREADS / 32];
    if ((tid & 31) == 0) warp_sums[tid >> 5] = acc;
    __syncthreads();

    if (tid == 0) {
        float v = 0.0f;
        #pragma unroll
        for (int w = 0; w < THREADS / 32; w++) v += warp_sums[w];

        atomicAdd(&g_accum, v);
        __threadfence();
        unsigned int done = atomicAdd(&g_count, 1u);
        if (done == (unsigned)(gridDim.x - 1)) {
            float total = atomicExch(&g_accum, 0.0f);   // read + reset scratch
            const float inv_total = 1.0f / ((float)NUM_SLICES * (float)SLICE_ELEMS);
            res[0] = total * inv_total;
            g_count = 0u;                               // reset for next replay
        }
    }
}

extern "C" void kernel_launch(void* const* d_in, const int* in_sizes, int n_in,
                              void* d_out, int out_size) {
    const float* out_t  = (const float*)d_in[0];  // "output"
    const float* conv_t = (const float*)d_in[1];  // "convdata"
    float* res = (float*)d_out;

    abs_diff_mean_kernel<<<BLOCKS, THREADS>>>(out_t, conv_t, res);
}

// round 12
// speedup vs baseline: 1.2657x; 1.0074x over previous
#include <cuda_runtime.h>

// Tensors [B=64, S=100, K=4, H=32, W=32] fp32; only channel k=3 is read:
// contiguous 1024-float run at s*4096 + 3072 for each of 6400 (b,s) slices.
// result = mean(|convdata[:,:,3] - output[:,:,3]|) over 6400*1024 elements.

static constexpr int NUM_SLICES   = 64 * 100;    // 6400
static constexpr int SLICE_STRIDE = 4 * 32 * 32; // 4096 floats per (b,s)
static constexpr int CH3_OFFSET   = 3 * 32 * 32; // 3072
static constexpr int SLICE_ELEMS  = 32 * 32;     // 1024 floats

static constexpr int THREADS = 256;              // one float4 per thread per slice
static constexpr int BLOCKS  = 400;              // strictly ONE wave (<=592 slots), perfectly balanced
static constexpr int SLICES_PER_BLOCK = NUM_SLICES / BLOCKS;  // 16
static constexpr int CHUNK   = 2;                // slices per pipeline stage (4 LDG.128)
static constexpr int NCHUNKS = SLICES_PER_BLOCK / CHUNK;      // 8

// Cross-block fan-in scratch (device globals: allocation-free).
// Invariant: zero at every launch; last finishing block re-zeros after publishing.
__device__ float        g_accum = 0.0f;
__device__ unsigned int g_count = 0u;

__global__ __launch_bounds__(THREADS, 4) void abs_diff_mean_kernel(
    const float* __restrict__ a,   // "output" tensor
    const float* __restrict__ b,   // "convdata" tensor
    float* __restrict__ res)
{
    const int tid = threadIdx.x;

    // This block's 16 contiguous slices; thread t owns one float4 per slice.
    const size_t base = (size_t)blockIdx.x * SLICES_PER_BLOCK * SLICE_STRIDE
                      + CH3_OFFSET + (size_t)tid * 4;
    const float* pa = a + base;
    const float* pb = b + base;

    float4 ca[CHUNK], cb[CHUNK];   // current chunk (being consumed)
    float4 na[CHUNK], nb[CHUNK];   // next chunk (in flight)

    // Prologue: chunk 0 in flight (4 independent LDG.128).
    #pragma unroll
    for (int i = 0; i < CHUNK; i++) {
        ca[i] = *reinterpret_cast<const float4*>(pa + i * SLICE_STRIDE);
        cb[i] = *reinterpret_cast<const float4*>(pb + i * SLICE_STRIDE);
    }

    float acc0 = 0.0f, acc1 = 0.0f;

    // Steady state: prefetch chunk c while consuming chunk c-1 (8 loads in flight).
    #pragma unroll
    for (int c = 1; c < NCHUNKS; c++) {
        #pragma unroll
        for (int i = 0; i < CHUNK; i++) {
            const int s = c * CHUNK + i;
            na[i] = *reinterpret_cast<const float4*>(pa + s * SLICE_STRIDE);
            nb[i] = *reinterpret_cast<const float4*>(pb + s * SLICE_STRIDE);
        }
        #pragma unroll
        for (int i = 0; i < CHUNK; i++) {
            acc0 += fabsf(cb[i].x - ca[i].x) + fabsf(cb[i].y - ca[i].y);
            acc1 += fabsf(cb[i].z - ca[i].z) + fabsf(cb[i].w - ca[i].w);
            ca[i] = na[i];
            cb[i] = nb[i];
        }
    }

    // Epilogue: consume final chunk.
    #pragma unroll
    for (int i = 0; i < CHUNK; i++) {
        acc0 += fabsf(cb[i].x - ca[i].x) + fabsf(cb[i].y - ca[i].y);
        acc1 += fabsf(cb[i].z - ca[i].z) + fabsf(cb[i].w - ca[i].w);
    }

    float acc = acc0 + acc1;

    // Warp reduce
    #pragma unroll
    for (int off = 16; off > 0; off >>= 1)
        acc += __shfl_xor_sync(0xFFFFFFFFu, acc, off);

    __shared__ float warp_sums[THREADS / 32];
    if ((tid & 31) == 0) warp_sums[tid >> 5] = acc;
    __syncthreads();

    if (tid == 0) {
        float v = 0.0f;
        #pragma unroll
        for (int w = 0; w < THREADS / 32; w++) v += warp_sums[w];

        atomicAdd(&g_accum, v);
        __threadfence();
        unsigned int done = atomicAdd(&g_count, 1u);
        if (done == (unsigned)(gridDim.x - 1)) {
            float total = atomicExch(&g_accum, 0.0f);   // read + reset scratch
            const float inv_total = 1.0f / ((float)NUM_SLICES * (float)SLICE_ELEMS);
            res[0] = total * inv_total;
            g_count = 0u;                               // reset for next replay
        }
    }
}

extern "C" void kernel_launch(void* const* d_in, const int* in_sizes, int n_in,
                              void* d_out, int out_size) {
    const float* out_t  = (const float*)d_in[0];  // "output"
    const float* conv_t = (const float*)d_in[1];  // "convdata"
    float* res = (float*)d_out;

    abs_diff_mean_kernel<<<BLOCKS, THREADS>>>(out_t, conv_t, res);
}